// round 9
// baseline (speedup 1.0000x reference)
#include <cuda_runtime.h>
#include <math.h>

#define N_NODES 50000
#define N_EDGES 800000

// ---------------- scratch (no cudaMalloc allowed) ----------------
__device__ float g_q[N_NODES * 128];
__device__ float g_k[N_NODES * 128];
__device__ float g_v[N_NODES * 128];
__device__ float g_skip[N_NODES * 32];
__device__ int   g_deg[N_NODES];
__device__ int   g_off[N_NODES];        // exclusive prefix; after scatter = inclusive end
__device__ int2  g_csr[N_EDGES];        // (src, bitcast(weight)) grouped by dst
__device__ int   g_bsums[64];
__device__ float g_y0t[N_NODES * 256];  // tf32-rounded [x, x*t]
__device__ float g_wc[256 * 416];       // tf32-rounded [Wq|Wk|Wv|Wskip]

__device__ __forceinline__ unsigned f2tf(float x) {
    unsigned r;
    asm("cvt.rna.tf32.f32 %0, %1;" : "=r"(r) : "f"(x));
    return r;
}

// ================= pre-convert =============================================
__global__ void conv_y0(const float* __restrict__ x, const float* __restrict__ t,
                        int n) {
    const int idx = blockIdx.x * blockDim.x + threadIdx.x;  // float4 index
    const int total = n * 64;
    if (idx >= total) return;
    const int m = idx >> 6;
    const int c4 = idx & 63;
    float4 v;
    if (c4 < 32) v = ((const float4*)x)[m * 32 + c4];
    else {
        v = ((const float4*)x)[m * 32 + (c4 - 32)];
        const float tm = t[m];
        v.x *= tm; v.y *= tm; v.z *= tm; v.w *= tm;
    }
    float4 o;
    o.x = __uint_as_float(f2tf(v.x));
    o.y = __uint_as_float(f2tf(v.y));
    o.z = __uint_as_float(f2tf(v.z));
    o.w = __uint_as_float(f2tf(v.w));
    ((float4*)g_y0t)[idx] = o;
}

__global__ void conv_w(const float* __restrict__ Wq, const float* __restrict__ Wk,
                       const float* __restrict__ Wv, const float* __restrict__ Ws) {
    for (int idx = blockIdx.x * blockDim.x + threadIdx.x; idx < 256 * 416;
         idx += gridDim.x * blockDim.x) {
        const int k = idx / 416;
        const int j = idx - k * 416;
        float v;
        if (j < 128)      v = Wq[k * 128 + j];
        else if (j < 256) v = Wk[k * 128 + (j - 128)];
        else if (j < 384) v = Wv[k * 128 + (j - 256)];
        else              v = Ws[k * 32 + (j - 384)];
        g_wc[idx] = __uint_as_float(f2tf(v));
    }
}

// ================= tf32 GEMM: proven tiles, cp.async, 3 CTA/SM =============
// BM=128, BN=128, BK=32. 256 thr = 8 warps (4m x 2n), warp tile 32x64.
// 2-stage cp.async from pre-converted tf32 buffers. No CVT in kernel.
#define BM 128
#define BN 128
#define BK 32
#define A_STRIDE 36        // frag banks 4g+tig -> conflict-free
#define B_STRIDE 136       // frag banks 8tig+g -> conflict-free
#define A_STAGE (BM * A_STRIDE)
#define B_STAGE (BK * B_STRIDE)
#define GSMEM_BYTES ((2 * A_STAGE + 2 * B_STAGE) * 4)

__device__ __forceinline__ void mma_tf32(float* c, const unsigned* a,
                                         unsigned b0, unsigned b1) {
    asm volatile(
        "mma.sync.aligned.m16n8k8.row.col.f32.tf32.tf32.f32 "
        "{%0,%1,%2,%3}, {%4,%5,%6,%7}, {%8,%9}, {%0,%1,%2,%3};\n"
        : "+f"(c[0]), "+f"(c[1]), "+f"(c[2]), "+f"(c[3])
        : "r"(a[0]), "r"(a[1]), "r"(a[2]), "r"(a[3]), "r"(b0), "r"(b1));
}

__device__ __forceinline__ void cpa16(unsigned dst, const void* src, int sz) {
    asm volatile("cp.async.cg.shared.global [%0], [%1], 16, %2;\n"
                 :: "r"(dst), "l"(src), "r"(sz));
}
__device__ __forceinline__ void cpa_commit() {
    asm volatile("cp.async.commit_group;\n");
}
__device__ __forceinline__ void cpa_wait1() {
    asm volatile("cp.async.wait_group 1;\n");
}

__global__ void __launch_bounds__(256, 3) gemm_tc(
    const float* __restrict__ bq, const float* __restrict__ bk,
    const float* __restrict__ bv, const float* __restrict__ bs,
    int n)
{
    extern __shared__ float sm[];
    float* As = sm;                   // [2][BM][A_STRIDE]
    float* Bs = sm + 2 * A_STAGE;     // [2][BK][B_STRIDE]

    const int m0 = blockIdx.x * BM;
    const int slice = blockIdx.y;
    const int colOff = slice * 128;
    const int bw = (slice == 3) ? 32 : 128;
    const float* bias;
    float* outp;
    if (slice == 0)      { bias = bq; outp = g_q; }
    else if (slice == 1) { bias = bk; outp = g_k; }
    else if (slice == 2) { bias = bv; outp = g_v; }
    else                 { bias = bs; outp = g_skip; }

    const int tid = threadIdx.x;
    const int lane = tid & 31;
    const int wid = tid >> 5;
    const int warp_m = wid & 3;
    const int warp_n = wid >> 2;
    const int g = lane >> 2;
    const int tig = lane & 3;

    float acc[2][8][4];
    #pragma unroll
    for (int mi = 0; mi < 2; mi++)
        #pragma unroll
        for (int ni = 0; ni < 8; ni++)
            #pragma unroll
            for (int c = 0; c < 4; c++) acc[mi][ni][c] = 0.f;

    // A copy: row = tid>>1, 4 chunks of 16B at ((tid&1)*4 + i)
    const int a_row = tid >> 1;
    const int a_mg = m0 + a_row;
    const float* a_src = g_y0t + (size_t)(a_mg < n ? a_mg : 0) * 256 + (tid & 1) * 16;
    const int a_sz = (a_mg < n) ? 16 : 0;
    const unsigned aBase = (unsigned)__cvta_generic_to_shared(As)
                         + a_row * (A_STRIDE * 4) + (tid & 1) * 64;
    const unsigned bBase = (unsigned)__cvta_generic_to_shared(Bs);
    // B copy: 1024 chunks, 4 per thread: c = tid + i*256; row=c>>5, col4=c&31
    const float* wcBase = g_wc + colOff;

    auto issue = [&](int s, int k0) {
        const unsigned adst = aBase + s * (A_STAGE * 4);
        const float* asrc = a_src + k0;
        #pragma unroll
        for (int i = 0; i < 4; i++)
            cpa16(adst + i * 16, asrc + i * 4, a_sz);
        const unsigned bdst = bBase + s * (B_STAGE * 4);
        #pragma unroll
        for (int i = 0; i < 4; i++) {
            const int c = tid + i * 256;
            const int row = c >> 5;
            const int c4 = c & 31;
            const int sz = (c4 * 4 < bw) ? 16 : 0;
            const float* bsrc = wcBase + (size_t)(k0 + row) * 416 + c4 * 4;
            cpa16(bdst + row * (B_STRIDE * 4) + c4 * 16, bsrc, sz);
        }
    };

    issue(0, 0);   cpa_commit();
    issue(1, 32);  cpa_commit();

    for (int it = 0; it < 8; it++) {
        const int s = it & 1;
        cpa_wait1();
        __syncthreads();

        const float* Asb = As + s * A_STAGE;
        const float* Bsb = Bs + s * B_STAGE;
        #pragma unroll
        for (int ks = 0; ks < 4; ks++) {
            const int kk = ks * 8;
            unsigned afrag[2][4];
            #pragma unroll
            for (int mi = 0; mi < 2; mi++) {
                const int r0 = warp_m * 32 + mi * 16 + g;
                afrag[mi][0] = __float_as_uint(Asb[r0 * A_STRIDE + kk + tig]);
                afrag[mi][1] = __float_as_uint(Asb[(r0 + 8) * A_STRIDE + kk + tig]);
                afrag[mi][2] = __float_as_uint(Asb[r0 * A_STRIDE + kk + tig + 4]);
                afrag[mi][3] = __float_as_uint(Asb[(r0 + 8) * A_STRIDE + kk + tig + 4]);
            }
            #pragma unroll
            for (int ni = 0; ni < 8; ni++) {
                const int cb = warp_n * 64 + ni * 8 + g;
                const unsigned b0 = __float_as_uint(Bsb[(kk + tig) * B_STRIDE + cb]);
                const unsigned b1 = __float_as_uint(Bsb[(kk + tig + 4) * B_STRIDE + cb]);
                mma_tf32(acc[0][ni], afrag[0], b0, b1);
                mma_tf32(acc[1][ni], afrag[1], b0, b1);
            }
        }
        __syncthreads();

        const int nk = (it + 2) * 32;
        if (nk < 256) issue(s, nk);
        cpa_commit();
    }

    #pragma unroll
    for (int mi = 0; mi < 2; mi++) {
        const int row = warp_m * 32 + mi * 16 + g;
        #pragma unroll
        for (int ni = 0; ni < 8; ni++) {
            const int col = warp_n * 64 + ni * 8 + 2 * tig;
            if (col >= bw) continue;
            const float bb0 = bias[col];
            const float bb1 = bias[col + 1];
            const int mg0 = m0 + row;
            const int mg1 = m0 + row + 8;
            if (mg0 < n) {
                float2 o; o.x = acc[mi][ni][0] + bb0; o.y = acc[mi][ni][1] + bb1;
                *(float2*)&outp[(size_t)mg0 * bw + col] = o;
            }
            if (mg1 < n) {
                float2 o; o.x = acc[mi][ni][2] + bb0; o.y = acc[mi][ni][3] + bb1;
                *(float2*)&outp[(size_t)mg1 * bw + col] = o;
            }
        }
    }
}

// ================= CSR build ===============================================
__global__ void count_deg(const int* __restrict__ ei, int nE) {
    const int e = blockIdx.x * blockDim.x + threadIdx.x;
    if (e < nE) atomicAdd(&g_deg[ei[nE + e]], 1);
}

#define SCAN_B 1024
__global__ void scan1(int n) {
    __shared__ int sh[SCAN_B];
    const int tid = threadIdx.x;
    const int i = blockIdx.x * SCAN_B + tid;
    const int v = (i < n) ? g_deg[i] : 0;
    sh[tid] = v;
    __syncthreads();
    #pragma unroll
    for (int off = 1; off < SCAN_B; off <<= 1) {
        int u = (tid >= off) ? sh[tid - off] : 0;
        __syncthreads();
        sh[tid] += u;
        __syncthreads();
    }
    if (i < n) g_off[i] = sh[tid] - v;   // exclusive
    if (tid == SCAN_B - 1) g_bsums[blockIdx.x] = sh[tid];
}

__global__ void scan2(int nb) {
    __shared__ int sh[64];
    const int tid = threadIdx.x;
    const int v = (tid < nb) ? g_bsums[tid] : 0;
    sh[tid] = v;
    __syncthreads();
    #pragma unroll
    for (int off = 1; off < 64; off <<= 1) {
        int u = (tid >= off) ? sh[tid - off] : 0;
        __syncthreads();
        sh[tid] += u;
        __syncthreads();
    }
    if (tid < nb) g_bsums[tid] = sh[tid] - v;  // exclusive
}

__global__ void scan3(int n) {
    const int i = blockIdx.x * SCAN_B + threadIdx.x;
    if (i < n && blockIdx.x > 0) g_off[i] += g_bsums[blockIdx.x];
}

// bump g_off[dst] directly: after this kernel g_off[dst] = inclusive end.
__global__ void scatter_csr(const int* __restrict__ ei,
                            const float* __restrict__ ew, int nE) {
    const int e = blockIdx.x * blockDim.x + threadIdx.x;
    if (e >= nE) return;
    const int src = ei[e];
    const int dst = ei[nE + e];
    const int pos = atomicAdd(&g_off[dst], 1);
    int2 sw;
    sw.x = src;
    sw.y = __float_as_int(ew[e]);
    g_csr[pos] = sw;
}

// ============ Fused node pass: attention aggregate + epilogue ==============
// One warp per destination node; 4-edge software pipeline for MLP. (R7 proven)
__global__ void __launch_bounds__(256) node_kernel(
    const float* __restrict__ x,
    const float* __restrict__ We, const float* __restrict__ be,
    const float* __restrict__ Wmlp, const float* __restrict__ bmlp,
    float* __restrict__ out, int n)
{
    __shared__ float w_sh[32 * 256];
    __shared__ float bm_sh[256];
    for (int i = threadIdx.x; i < 32 * 256; i += 256) w_sh[i] = Wmlp[i];
    if (threadIdx.x < 256) bm_sh[threadIdx.x] = bmlp[threadIdx.x];
    __syncthreads();

    const int warp = threadIdx.x >> 5;
    const int lane = threadIdx.x & 31;
    const int nn = blockIdx.x * 8 + warp;
    if (nn >= n) return;

    const float4 We4 = ((const float4*)We)[lane];
    const float4 be4 = ((const float4*)be)[lane];
    const float4 q4 = ((const float4*)g_q)[nn * 32 + lane];

    const int cnt = g_deg[nn];
    const int end = g_off[nn];          // inclusive end (scatter bumped it)
    const int beg = end - cnt;

    float4 macc = make_float4(0.f, 0.f, 0.f, 0.f);
    float dsum = 0.f;

    int j = beg;
    const int lim = beg + (cnt & ~3);
    for (; j < lim; j += 4) {
        int2 sw[4];
        #pragma unroll
        for (int i = 0; i < 4; i++) sw[i] = g_csr[j + i];
        float4 kv[4], vv[4];
        #pragma unroll
        for (int i = 0; i < 4; i++) {
            kv[i] = ((const float4*)g_k)[sw[i].x * 32 + lane];
            vv[i] = ((const float4*)g_v)[sw[i].x * 32 + lane];
        }
        float s[4];
        #pragma unroll
        for (int i = 0; i < 4; i++) {
            const float wt = __int_as_float(sw[i].y);
            const float ex = fmaf(wt, We4.x, be4.x);
            const float ey = fmaf(wt, We4.y, be4.y);
            const float ez = fmaf(wt, We4.z, be4.z);
            const float ew_ = fmaf(wt, We4.w, be4.w);
            kv[i].x += ex; kv[i].y += ey; kv[i].z += ez; kv[i].w += ew_;
            vv[i].x += ex; vv[i].y += ey; vv[i].z += ez; vv[i].w += ew_;
            s[i] = q4.x * kv[i].x + q4.y * kv[i].y + q4.z * kv[i].z + q4.w * kv[i].w;
        }
        #pragma unroll
        for (int i = 0; i < 4; i++) {
            s[i] += __shfl_xor_sync(0xffffffffu, s[i], 1);
            s[i] += __shfl_xor_sync(0xffffffffu, s[i], 2);
            s[i] += __shfl_xor_sync(0xffffffffu, s[i], 4);
        }
        #pragma unroll
        for (int i = 0; i < 4; i++) {
            const float p = __expf(s[i] * 0.17677669529663689f);  // 1/sqrt(32)
            dsum += p;
            macc.x = fmaf(vv[i].x, p, macc.x);
            macc.y = fmaf(vv[i].y, p, macc.y);
            macc.z = fmaf(vv[i].z, p, macc.z);
            macc.w = fmaf(vv[i].w, p, macc.w);
        }
    }
    for (; j < end; j++) {
        const int2 sw = g_csr[j];
        const float wt = __int_as_float(sw.y);
        const float ex = fmaf(wt, We4.x, be4.x);
        const float ey = fmaf(wt, We4.y, be4.y);
        const float ez = fmaf(wt, We4.z, be4.z);
        const float ew_ = fmaf(wt, We4.w, be4.w);
        float4 kv = ((const float4*)g_k)[sw.x * 32 + lane];
        float4 vv = ((const float4*)g_v)[sw.x * 32 + lane];
        kv.x += ex; kv.y += ey; kv.z += ez; kv.w += ew_;
        vv.x += ex; vv.y += ey; vv.z += ez; vv.w += ew_;
        float s = q4.x * kv.x + q4.y * kv.y + q4.z * kv.z + q4.w * kv.w;
        s += __shfl_xor_sync(0xffffffffu, s, 1);
        s += __shfl_xor_sync(0xffffffffu, s, 2);
        s += __shfl_xor_sync(0xffffffffu, s, 4);
        const float p = __expf(s * 0.17677669529663689f);
        dsum += p;
        macc.x = fmaf(vv.x, p, macc.x);
        macc.y = fmaf(vv.y, p, macc.y);
        macc.z = fmaf(vv.z, p, macc.z);
        macc.w = fmaf(vv.w, p, macc.w);
    }

    const float inv = 1.f / (dsum + 1e-16f);
    float4 z4;
    z4.x = macc.x * inv; z4.y = macc.y * inv;
    z4.z = macc.z * inv; z4.w = macc.w * inv;

    #pragma unroll
    for (int m = 8; m <= 16; m <<= 1) {
        z4.x += __shfl_xor_sync(0xffffffffu, z4.x, m);
        z4.y += __shfl_xor_sync(0xffffffffu, z4.y, m);
        z4.z += __shfl_xor_sync(0xffffffffu, z4.z, m);
        z4.w += __shfl_xor_sync(0xffffffffu, z4.w, m);
    }

    const int u = lane & 7;
    const float4 sk = ((const float4*)g_skip)[nn * 8 + u];
    float4 y4;
    y4.x = tanhf(z4.x * 0.25f + sk.x);
    y4.y = tanhf(z4.y * 0.25f + sk.y);
    y4.z = tanhf(z4.z * 0.25f + sk.z);
    y4.w = tanhf(z4.w * 0.25f + sk.w);

    float accS[4] = {0.f, 0.f, 0.f, 0.f};
    float accH[4] = {0.f, 0.f, 0.f, 0.f};
    #pragma unroll
    for (int uu = 0; uu < 8; uu++) {
        const float b0 = __shfl_sync(0xffffffffu, y4.x, uu);
        const float b1 = __shfl_sync(0xffffffffu, y4.y, uu);
        const float b2 = __shfl_sync(0xffffffffu, y4.z, uu);
        const float b3 = __shfl_sync(0xffffffffu, y4.w, uu);
        const int d0 = 4 * uu;
        #pragma unroll
        for (int k = 0; k < 4; k++) {
            const int c = lane + 32 * k;
            accS[k] = fmaf(b0, w_sh[(d0 + 0) * 256 + c], accS[k]);
            accS[k] = fmaf(b1, w_sh[(d0 + 1) * 256 + c], accS[k]);
            accS[k] = fmaf(b2, w_sh[(d0 + 2) * 256 + c], accS[k]);
            accS[k] = fmaf(b3, w_sh[(d0 + 3) * 256 + c], accS[k]);
            accH[k] = fmaf(b0, w_sh[(d0 + 0) * 256 + 128 + c], accH[k]);
            accH[k] = fmaf(b1, w_sh[(d0 + 1) * 256 + 128 + c], accH[k]);
            accH[k] = fmaf(b2, w_sh[(d0 + 2) * 256 + 128 + c], accH[k]);
            accH[k] = fmaf(b3, w_sh[(d0 + 3) * 256 + 128 + c], accH[k]);
        }
    }
    #pragma unroll
    for (int k = 0; k < 4; k++) {
        const int c = lane + 32 * k;
        const float sc = tanhf(accS[k] + bm_sh[c]);
        const float sh = tanhf(accH[k] + bm_sh[128 + c]);
        out[(size_t)nn * 128 + c] = fmaf(x[(size_t)nn * 128 + c], sc, sh);
    }
}

// ================= launch ==================================================
extern "C" void kernel_launch(void* const* d_in, const int* in_sizes, int n_in,
                              void* d_out, int out_size)
{
    const float* x     = (const float*)d_in[0];
    const float* t     = (const float*)d_in[1];
    const int*   ei    = (const int*)  d_in[2];
    const float* ew    = (const float*)d_in[3];
    const float* Wq    = (const float*)d_in[4];
    const float* bq    = (const float*)d_in[5];
    const float* Wk    = (const float*)d_in[6];
    const float* bk    = (const float*)d_in[7];
    const float* Wv    = (const float*)d_in[8];
    const float* bv    = (const float*)d_in[9];
    const float* We    = (const float*)d_in[10];
    const float* be    = (const float*)d_in[11];
    const float* Wskip = (const float*)d_in[12];
    const float* bskip = (const float*)d_in[13];
    const float* Wmlp  = (const float*)d_in[14];
    const float* bmlp  = (const float*)d_in[15];
    float* out = (float*)d_out;

    const int n  = in_sizes[0] / 128;
    const int nE = in_sizes[3];

    // one-time side stream + fork/join events (same work every call)
    static cudaStream_t sB = nullptr;
    static cudaEvent_t evFork = nullptr, evW = nullptr, evJoin = nullptr;
    if (sB == nullptr) {
        cudaStreamCreateWithFlags(&sB, cudaStreamNonBlocking);
        cudaEventCreateWithFlags(&evFork, cudaEventDisableTiming);
        cudaEventCreateWithFlags(&evW, cudaEventDisableTiming);
        cudaEventCreateWithFlags(&evJoin, cudaEventDisableTiming);
    }

    cudaFuncSetAttribute(gemm_tc, cudaFuncAttributeMaxDynamicSharedMemorySize,
                         GSMEM_BYTES);

    void *degPtr = nullptr;
    cudaGetSymbolAddress(&degPtr, g_deg);

    // ---- fork ------------------------------------------------------------
    cudaEventRecord(evFork, 0);
    cudaStreamWaitEvent(sB, evFork, 0);

    // side: weight convert first (GEMM needs it), then CSR build
    conv_w<<<104, 1024, 0, sB>>>(Wq, Wk, Wv, Wskip);
    cudaEventRecord(evW, sB);
    cudaMemsetAsync(degPtr, 0, (size_t)n * sizeof(int), sB);
    count_deg<<<(nE + 255) / 256, 256, 0, sB>>>(ei, nE);
    const int nb = (n + SCAN_B - 1) / SCAN_B;
    scan1<<<nb, SCAN_B, 0, sB>>>(n);
    scan2<<<1, 64, 0, sB>>>(nb);
    scan3<<<nb, SCAN_B, 0, sB>>>(n);
    scatter_csr<<<(nE + 255) / 256, 256, 0, sB>>>(ei, ew, nE);
    cudaEventRecord(evJoin, sB);

    // main: y0 convert, then GEMM (waits for conv_w)
    conv_y0<<<(n * 64 + 255) / 256, 256>>>(x, t, n);
    cudaStreamWaitEvent(0, evW, 0);
    const int gm = (n + BM - 1) / BM;
    gemm_tc<<<dim3(gm, 4), 256, GSMEM_BYTES>>>(bq, bk, bv, bskip, n);

    // ---- join, then fused attention + epilogue ---------------------------
    cudaStreamWaitEvent(0, evJoin, 0);
    node_kernel<<<(n + 7) / 8, 256>>>(x, We, be, Wmlp, bmlp, out, n);
}

// round 10
// speedup vs baseline: 1.1719x; 1.1719x over previous
#include <cuda_runtime.h>
#include <cuda_fp16.h>
#include <math.h>

#define N_NODES 50000
#define N_EDGES 800000

// ---------------- scratch (no cudaMalloc allowed) ----------------
__device__ float  g_q[N_NODES * 128];
__device__ __half g_kh[N_NODES * 128];
__device__ __half g_vh[N_NODES * 128];
__device__ float  g_skip[N_NODES * 32];
__device__ int    g_deg[N_NODES];
__device__ int    g_off[N_NODES];       // exclusive prefix; after scatter = inclusive end
__device__ int2   g_csr[N_EDGES];       // (src, bitcast(weight)) grouped by dst
__device__ int    g_bsums[64];

// ================= tf32 tensor-core GEMM (proven R2/R7 style) ==============
#define BM 128
#define BN 128
#define BK 32

__device__ __forceinline__ unsigned f2tf(float x) {
    unsigned r;
    asm("cvt.rna.tf32.f32 %0, %1;" : "=r"(r) : "f"(x));
    return r;
}

__device__ __forceinline__ void mma_tf32(float* c, const unsigned* a,
                                         unsigned b0, unsigned b1) {
    asm volatile(
        "mma.sync.aligned.m16n8k8.row.col.f32.tf32.tf32.f32 "
        "{%0,%1,%2,%3}, {%4,%5,%6,%7}, {%8,%9}, {%0,%1,%2,%3};\n"
        : "+f"(c[0]), "+f"(c[1]), "+f"(c[2]), "+f"(c[3])
        : "r"(a[0]), "r"(a[1]), "r"(a[2]), "r"(a[3]), "r"(b0), "r"(b1));
}

__global__ void __launch_bounds__(256, 2) gemm_tf32(
    const float* __restrict__ x, const float* __restrict__ t,
    const float* __restrict__ Wq, const float* __restrict__ bq,
    const float* __restrict__ Wk, const float* __restrict__ bk,
    const float* __restrict__ Wv, const float* __restrict__ bv,
    const float* __restrict__ Ws, const float* __restrict__ bs,
    int n)
{
    __shared__ float As[BM][BK + 4];
    __shared__ float Bs[BK][BN + 8];

    const int m0 = blockIdx.x * BM;
    const int slice = blockIdx.y;

    const float* Bmat; const float* bias; float* outp = nullptr;
    __half* houtp = nullptr; int bw;
    if (slice == 0)      { Bmat = Wq; bias = bq; outp  = g_q;    bw = 128; }
    else if (slice == 1) { Bmat = Wk; bias = bk; houtp = g_kh;   bw = 128; }
    else if (slice == 2) { Bmat = Wv; bias = bv; houtp = g_vh;   bw = 128; }
    else                 { Bmat = Ws; bias = bs; outp  = g_skip; bw = 32;  }

    const int tid = threadIdx.x;
    const int lane = tid & 31;
    const int wid = tid >> 5;
    const int warp_m = wid & 3;
    const int warp_n = wid >> 2;
    const int g = lane >> 2;
    const int tig = lane & 3;

    float acc[2][8][4];
    #pragma unroll
    for (int mi = 0; mi < 2; mi++)
        #pragma unroll
        for (int ni = 0; ni < 8; ni++)
            #pragma unroll
            for (int c = 0; c < 4; c++) acc[mi][ni][c] = 0.f;

    float4 ar[4];
    float4 br[4];

    const int a_row = tid >> 1;
    const int a_f4  = (tid & 1) * 4;
    const int b_col4 = tid & 31;

    auto loadA = [&](int k0) {
        const int mg = m0 + a_row;
        const int xbase = (k0 < 128 ? k0 : k0 - 128);
        float mult = 0.f;
        if (mg < n) mult = (k0 < 128) ? 1.f : t[mg];
        const float4* xr = (const float4*)&x[(size_t)(mg < n ? mg : 0) * 128 + xbase];
        #pragma unroll
        for (int i = 0; i < 4; i++) {
            float4 v = xr[a_f4 + i];
            ar[i].x = v.x * mult; ar[i].y = v.y * mult;
            ar[i].z = v.z * mult; ar[i].w = v.w * mult;
        }
    };
    auto storeA = [&]() {
        #pragma unroll
        for (int i = 0; i < 4; i++) {
            float4 v;
            v.x = __uint_as_float(f2tf(ar[i].x));
            v.y = __uint_as_float(f2tf(ar[i].y));
            v.z = __uint_as_float(f2tf(ar[i].z));
            v.w = __uint_as_float(f2tf(ar[i].w));
            *(float4*)&As[a_row][(a_f4 + i) * 4] = v;
        }
    };
    auto loadB = [&](int k0) {
        const int jj = b_col4 * 4;
        #pragma unroll
        for (int i = 0; i < 4; i++) {
            const int row = wid + i * 8;
            if (jj < bw) br[i] = *(const float4*)&Bmat[(size_t)(k0 + row) * bw + jj];
            else         br[i] = make_float4(0.f, 0.f, 0.f, 0.f);
        }
    };
    auto storeB = [&]() {
        const int jj = b_col4 * 4;
        #pragma unroll
        for (int i = 0; i < 4; i++) {
            const int row = wid + i * 8;
            float4 v;
            v.x = __uint_as_float(f2tf(br[i].x));
            v.y = __uint_as_float(f2tf(br[i].y));
            v.z = __uint_as_float(f2tf(br[i].z));
            v.w = __uint_as_float(f2tf(br[i].w));
            *(float4*)&Bs[row][jj] = v;
        }
    };

    loadA(0); loadB(0);
    storeA(); storeB();
    __syncthreads();

    for (int k0 = 0; k0 < 256; k0 += BK) {
        const bool has_next = (k0 + BK) < 256;
        if (has_next) { loadA(k0 + BK); loadB(k0 + BK); }

        #pragma unroll
        for (int ks = 0; ks < 4; ks++) {
            const int kk = ks * 8;
            unsigned afrag[2][4];
            #pragma unroll
            for (int mi = 0; mi < 2; mi++) {
                const int r0 = warp_m * 32 + mi * 16 + g;
                afrag[mi][0] = __float_as_uint(As[r0][kk + tig]);
                afrag[mi][1] = __float_as_uint(As[r0 + 8][kk + tig]);
                afrag[mi][2] = __float_as_uint(As[r0][kk + tig + 4]);
                afrag[mi][3] = __float_as_uint(As[r0 + 8][kk + tig + 4]);
            }
            #pragma unroll
            for (int ni = 0; ni < 8; ni++) {
                const int cb = warp_n * 64 + ni * 8 + g;
                const unsigned b0 = __float_as_uint(Bs[kk + tig][cb]);
                const unsigned b1 = __float_as_uint(Bs[kk + tig + 4][cb]);
                mma_tf32(acc[0][ni], afrag[0], b0, b1);
                mma_tf32(acc[1][ni], afrag[1], b0, b1);
            }
        }
        __syncthreads();
        if (has_next) { storeA(); storeB(); __syncthreads(); }
    }

    #pragma unroll
    for (int mi = 0; mi < 2; mi++) {
        const int row = warp_m * 32 + mi * 16 + g;
        #pragma unroll
        for (int ni = 0; ni < 8; ni++) {
            const int col = warp_n * 64 + ni * 8 + 2 * tig;
            if (col >= bw) continue;
            const float bb0 = bias[col];
            const float bb1 = bias[col + 1];
            const int mg0 = m0 + row;
            const int mg1 = m0 + row + 8;
            if (houtp) {
                if (mg0 < n) {
                    __half2 h = __floats2half2_rn(acc[mi][ni][0] + bb0,
                                                  acc[mi][ni][1] + bb1);
                    *(__half2*)&houtp[(size_t)mg0 * 128 + col] = h;
                }
                if (mg1 < n) {
                    __half2 h = __floats2half2_rn(acc[mi][ni][2] + bb0,
                                                  acc[mi][ni][3] + bb1);
                    *(__half2*)&houtp[(size_t)mg1 * 128 + col] = h;
                }
            } else {
                if (mg0 < n) {
                    float2 o; o.x = acc[mi][ni][0] + bb0; o.y = acc[mi][ni][1] + bb1;
                    *(float2*)&outp[(size_t)mg0 * bw + col] = o;
                }
                if (mg1 < n) {
                    float2 o; o.x = acc[mi][ni][2] + bb0; o.y = acc[mi][ni][3] + bb1;
                    *(float2*)&outp[(size_t)mg1 * bw + col] = o;
                }
            }
        }
    }
}

// ================= CSR build ===============================================
__global__ void count_deg(const int* __restrict__ ei, int nE) {
    const int e = blockIdx.x * blockDim.x + threadIdx.x;
    if (e < nE) atomicAdd(&g_deg[ei[nE + e]], 1);
}

#define SCAN_B 1024
__global__ void scan1(int n) {
    __shared__ int sh[SCAN_B];
    const int tid = threadIdx.x;
    const int i = blockIdx.x * SCAN_B + tid;
    const int v = (i < n) ? g_deg[i] : 0;
    sh[tid] = v;
    __syncthreads();
    #pragma unroll
    for (int off = 1; off < SCAN_B; off <<= 1) {
        int u = (tid >= off) ? sh[tid - off] : 0;
        __syncthreads();
        sh[tid] += u;
        __syncthreads();
    }
    if (i < n) g_off[i] = sh[tid] - v;   // exclusive
    if (tid == SCAN_B - 1) g_bsums[blockIdx.x] = sh[tid];
}

__global__ void scan2(int nb) {
    __shared__ int sh[64];
    const int tid = threadIdx.x;
    const int v = (tid < nb) ? g_bsums[tid] : 0;
    sh[tid] = v;
    __syncthreads();
    #pragma unroll
    for (int off = 1; off < 64; off <<= 1) {
        int u = (tid >= off) ? sh[tid - off] : 0;
        __syncthreads();
        sh[tid] += u;
        __syncthreads();
    }
    if (tid < nb) g_bsums[tid] = sh[tid] - v;  // exclusive
}

__global__ void scan3(int n) {
    const int i = blockIdx.x * SCAN_B + threadIdx.x;
    if (i < n && blockIdx.x > 0) g_off[i] += g_bsums[blockIdx.x];
}

// bump g_off[dst] directly: after this kernel g_off[dst] = inclusive end.
__global__ void scatter_csr(const int* __restrict__ ei,
                            const float* __restrict__ ew, int nE) {
    const int e = blockIdx.x * blockDim.x + threadIdx.x;
    if (e >= nE) return;
    const int src = ei[e];
    const int dst = ei[nE + e];
    const int pos = atomicAdd(&g_off[dst], 1);
    int2 sw;
    sw.x = src;
    sw.y = __float_as_int(ew[e]);
    g_csr[pos] = sw;
}

// ============ Fused node pass: attention aggregate + epilogue ==============
// One warp per destination node; 4-edge software pipeline. k,v gathered fp16.
__device__ __forceinline__ float4 ldkv_h(const __half* basep, int src, int lane) {
    const uint2 raw = ((const uint2*)basep)[src * 32 + lane];
    const __half2 h01 = *(const __half2*)&raw.x;
    const __half2 h23 = *(const __half2*)&raw.y;
    const float2 f01 = __half22float2(h01);
    const float2 f23 = __half22float2(h23);
    return make_float4(f01.x, f01.y, f23.x, f23.y);
}

__global__ void __launch_bounds__(256) node_kernel(
    const float* __restrict__ x,
    const float* __restrict__ We, const float* __restrict__ be,
    const float* __restrict__ Wmlp, const float* __restrict__ bmlp,
    float* __restrict__ out, int n)
{
    __shared__ float w_sh[32 * 256];
    __shared__ float bm_sh[256];
    for (int i = threadIdx.x; i < 32 * 256; i += 256) w_sh[i] = Wmlp[i];
    if (threadIdx.x < 256) bm_sh[threadIdx.x] = bmlp[threadIdx.x];
    __syncthreads();

    const int warp = threadIdx.x >> 5;
    const int lane = threadIdx.x & 31;
    const int nn = blockIdx.x * 8 + warp;
    if (nn >= n) return;

    const float4 We4 = ((const float4*)We)[lane];
    const float4 be4 = ((const float4*)be)[lane];
    const float4 q4 = ((const float4*)g_q)[nn * 32 + lane];

    const int cnt = g_deg[nn];
    const int end = g_off[nn];          // inclusive end (scatter bumped it)
    const int beg = end - cnt;

    float4 macc = make_float4(0.f, 0.f, 0.f, 0.f);
    float dsum = 0.f;

    int j = beg;
    const int lim = beg + (cnt & ~3);
    for (; j < lim; j += 4) {
        int2 sw[4];
        #pragma unroll
        for (int i = 0; i < 4; i++) sw[i] = g_csr[j + i];
        float4 kv[4], vv[4];
        #pragma unroll
        for (int i = 0; i < 4; i++) {
            kv[i] = ldkv_h(g_kh, sw[i].x, lane);
            vv[i] = ldkv_h(g_vh, sw[i].x, lane);
        }
        float s[4];
        #pragma unroll
        for (int i = 0; i < 4; i++) {
            const float wt = __int_as_float(sw[i].y);
            const float ex = fmaf(wt, We4.x, be4.x);
            const float ey = fmaf(wt, We4.y, be4.y);
            const float ez = fmaf(wt, We4.z, be4.z);
            const float ew_ = fmaf(wt, We4.w, be4.w);
            kv[i].x += ex; kv[i].y += ey; kv[i].z += ez; kv[i].w += ew_;
            vv[i].x += ex; vv[i].y += ey; vv[i].z += ez; vv[i].w += ew_;
            s[i] = q4.x * kv[i].x + q4.y * kv[i].y + q4.z * kv[i].z + q4.w * kv[i].w;
        }
        #pragma unroll
        for (int i = 0; i < 4; i++) {
            s[i] += __shfl_xor_sync(0xffffffffu, s[i], 1);
            s[i] += __shfl_xor_sync(0xffffffffu, s[i], 2);
            s[i] += __shfl_xor_sync(0xffffffffu, s[i], 4);
        }
        #pragma unroll
        for (int i = 0; i < 4; i++) {
            const float p = __expf(s[i] * 0.17677669529663689f);  // 1/sqrt(32)
            dsum += p;
            macc.x = fmaf(vv[i].x, p, macc.x);
            macc.y = fmaf(vv[i].y, p, macc.y);
            macc.z = fmaf(vv[i].z, p, macc.z);
            macc.w = fmaf(vv[i].w, p, macc.w);
        }
    }
    for (; j < end; j++) {
        const int2 sw = g_csr[j];
        const float wt = __int_as_float(sw.y);
        const float ex = fmaf(wt, We4.x, be4.x);
        const float ey = fmaf(wt, We4.y, be4.y);
        const float ez = fmaf(wt, We4.z, be4.z);
        const float ew_ = fmaf(wt, We4.w, be4.w);
        float4 kv = ldkv_h(g_kh, sw.x, lane);
        float4 vv = ldkv_h(g_vh, sw.x, lane);
        kv.x += ex; kv.y += ey; kv.z += ez; kv.w += ew_;
        vv.x += ex; vv.y += ey; vv.z += ez; vv.w += ew_;
        float s = q4.x * kv.x + q4.y * kv.y + q4.z * kv.z + q4.w * kv.w;
        s += __shfl_xor_sync(0xffffffffu, s, 1);
        s += __shfl_xor_sync(0xffffffffu, s, 2);
        s += __shfl_xor_sync(0xffffffffu, s, 4);
        const float p = __expf(s * 0.17677669529663689f);
        dsum += p;
        macc.x = fmaf(vv.x, p, macc.x);
        macc.y = fmaf(vv.y, p, macc.y);
        macc.z = fmaf(vv.z, p, macc.z);
        macc.w = fmaf(vv.w, p, macc.w);
    }

    const float inv = 1.f / (dsum + 1e-16f);
    float4 z4;
    z4.x = macc.x * inv; z4.y = macc.y * inv;
    z4.z = macc.z * inv; z4.w = macc.w * inv;

    #pragma unroll
    for (int m = 8; m <= 16; m <<= 1) {
        z4.x += __shfl_xor_sync(0xffffffffu, z4.x, m);
        z4.y += __shfl_xor_sync(0xffffffffu, z4.y, m);
        z4.z += __shfl_xor_sync(0xffffffffu, z4.z, m);
        z4.w += __shfl_xor_sync(0xffffffffu, z4.w, m);
    }

    const int u = lane & 7;
    const float4 sk = ((const float4*)g_skip)[nn * 8 + u];
    float4 y4;
    y4.x = tanhf(z4.x * 0.25f + sk.x);
    y4.y = tanhf(z4.y * 0.25f + sk.y);
    y4.z = tanhf(z4.z * 0.25f + sk.z);
    y4.w = tanhf(z4.w * 0.25f + sk.w);

    float accS[4] = {0.f, 0.f, 0.f, 0.f};
    float accH[4] = {0.f, 0.f, 0.f, 0.f};
    #pragma unroll
    for (int uu = 0; uu < 8; uu++) {
        const float b0 = __shfl_sync(0xffffffffu, y4.x, uu);
        const float b1 = __shfl_sync(0xffffffffu, y4.y, uu);
        const float b2 = __shfl_sync(0xffffffffu, y4.z, uu);
        const float b3 = __shfl_sync(0xffffffffu, y4.w, uu);
        const int d0 = 4 * uu;
        #pragma unroll
        for (int k = 0; k < 4; k++) {
            const int c = lane + 32 * k;
            accS[k] = fmaf(b0, w_sh[(d0 + 0) * 256 + c], accS[k]);
            accS[k] = fmaf(b1, w_sh[(d0 + 1) * 256 + c], accS[k]);
            accS[k] = fmaf(b2, w_sh[(d0 + 2) * 256 + c], accS[k]);
            accS[k] = fmaf(b3, w_sh[(d0 + 3) * 256 + c], accS[k]);
            accH[k] = fmaf(b0, w_sh[(d0 + 0) * 256 + 128 + c], accH[k]);
            accH[k] = fmaf(b1, w_sh[(d0 + 1) * 256 + 128 + c], accH[k]);
            accH[k] = fmaf(b2, w_sh[(d0 + 2) * 256 + 128 + c], accH[k]);
            accH[k] = fmaf(b3, w_sh[(d0 + 3) * 256 + 128 + c], accH[k]);
        }
    }
    #pragma unroll
    for (int k = 0; k < 4; k++) {
        const int c = lane + 32 * k;
        const float sc = tanhf(accS[k] + bm_sh[c]);
        const float sh = tanhf(accH[k] + bm_sh[128 + c]);
        out[(size_t)nn * 128 + c] = fmaf(x[(size_t)nn * 128 + c], sc, sh);
    }
}

// ================= launch ==================================================
extern "C" void kernel_launch(void* const* d_in, const int* in_sizes, int n_in,
                              void* d_out, int out_size)
{
    const float* x     = (const float*)d_in[0];
    const float* t     = (const float*)d_in[1];
    const int*   ei    = (const int*)  d_in[2];
    const float* ew    = (const float*)d_in[3];
    const float* Wq    = (const float*)d_in[4];
    const float* bq    = (const float*)d_in[5];
    const float* Wk    = (const float*)d_in[6];
    const float* bk    = (const float*)d_in[7];
    const float* Wv    = (const float*)d_in[8];
    const float* bv    = (const float*)d_in[9];
    const float* We    = (const float*)d_in[10];
    const float* be    = (const float*)d_in[11];
    const float* Wskip = (const float*)d_in[12];
    const float* bskip = (const float*)d_in[13];
    const float* Wmlp  = (const float*)d_in[14];
    const float* bmlp  = (const float*)d_in[15];
    float* out = (float*)d_out;

    const int n  = in_sizes[0] / 128;
    const int nE = in_sizes[3];

    // one-time side stream + fork/join events (same work every call)
    static cudaStream_t sB = nullptr;
    static cudaEvent_t evFork = nullptr, evJoin = nullptr;
    if (sB == nullptr) {
        cudaStreamCreateWithFlags(&sB, cudaStreamNonBlocking);
        cudaEventCreateWithFlags(&evFork, cudaEventDisableTiming);
        cudaEventCreateWithFlags(&evJoin, cudaEventDisableTiming);
    }

    void *degPtr = nullptr;
    cudaGetSymbolAddress(&degPtr, g_deg);

    // ---- fork: CSR build on side stream, GEMM on main stream -------------
    cudaEventRecord(evFork, 0);
    cudaStreamWaitEvent(sB, evFork, 0);

    cudaMemsetAsync(degPtr, 0, (size_t)n * sizeof(int), sB);
    count_deg<<<(nE + 255) / 256, 256, 0, sB>>>(ei, nE);
    const int nb = (n + SCAN_B - 1) / SCAN_B;
    scan1<<<nb, SCAN_B, 0, sB>>>(n);
    scan2<<<1, 64, 0, sB>>>(nb);
    scan3<<<nb, SCAN_B, 0, sB>>>(n);
    scatter_csr<<<(nE + 255) / 256, 256, 0, sB>>>(ei, ew, nE);
    cudaEventRecord(evJoin, sB);

    dim3 g1((n + BM - 1) / BM, 4);
    gemm_tf32<<<g1, 256>>>(x, t, Wq, bq, Wk, bk, Wv, bv, Wskip, bskip, n);

    // ---- join, then fused attention + epilogue ---------------------------
    cudaStreamWaitEvent(0, evJoin, 0);
    node_kernel<<<(n + 7) / 8, 256>>>(x, We, be, Wmlp, bmlp, out, n);
}

// round 11
// speedup vs baseline: 1.2225x; 1.0433x over previous
#include <cuda_runtime.h>
#include <cuda_fp16.h>
#include <math.h>

#define N_NODES 50000
#define N_EDGES 800000

// ---------------- scratch (no cudaMalloc allowed) ----------------
__device__ float  g_q[N_NODES * 128];
__device__ __half g_kvh[N_NODES * 256];  // packed per row: [k(4)|v(4)] x 32 lanes
__device__ float  g_skip[N_NODES * 32];
__device__ int    g_deg[N_NODES];
__device__ int    g_off[N_NODES];       // exclusive prefix; after scatter = inclusive end
__device__ int2   g_csr[N_EDGES];       // (src, bitcast(weight)) grouped by dst
__device__ int    g_bsums[64];

// ================= tf32 tensor-core GEMM (proven R2/R7 style) ==============
#define BM 128
#define BN 128
#define BK 32

__device__ __forceinline__ unsigned f2tf(float x) {
    unsigned r;
    asm("cvt.rna.tf32.f32 %0, %1;" : "=r"(r) : "f"(x));
    return r;
}

__device__ __forceinline__ void mma_tf32(float* c, const unsigned* a,
                                         unsigned b0, unsigned b1) {
    asm volatile(
        "mma.sync.aligned.m16n8k8.row.col.f32.tf32.tf32.f32 "
        "{%0,%1,%2,%3}, {%4,%5,%6,%7}, {%8,%9}, {%0,%1,%2,%3};\n"
        : "+f"(c[0]), "+f"(c[1]), "+f"(c[2]), "+f"(c[3])
        : "r"(a[0]), "r"(a[1]), "r"(a[2]), "r"(a[3]), "r"(b0), "r"(b1));
}

__global__ void __launch_bounds__(256, 2) gemm_tf32(
    const float* __restrict__ x, const float* __restrict__ t,
    const float* __restrict__ Wq, const float* __restrict__ bq,
    const float* __restrict__ Wk, const float* __restrict__ bk,
    const float* __restrict__ Wv, const float* __restrict__ bv,
    const float* __restrict__ Ws, const float* __restrict__ bs,
    int n)
{
    __shared__ float As[BM][BK + 4];
    __shared__ float Bs[BK][BN + 8];

    const int m0 = blockIdx.x * BM;
    const int slice = blockIdx.y;

    const float* Bmat; const float* bias; float* outp = nullptr;
    int voff = 0; bool packed = false; int bw;
    if (slice == 0)      { Bmat = Wq; bias = bq; outp = g_q;    bw = 128; }
    else if (slice == 1) { Bmat = Wk; bias = bk; packed = true; voff = 0; bw = 128; }
    else if (slice == 2) { Bmat = Wv; bias = bv; packed = true; voff = 4; bw = 128; }
    else                 { Bmat = Ws; bias = bs; outp = g_skip; bw = 32;  }

    const int tid = threadIdx.x;
    const int lane = tid & 31;
    const int wid = tid >> 5;
    const int warp_m = wid & 3;
    const int warp_n = wid >> 2;
    const int g = lane >> 2;
    const int tig = lane & 3;

    float acc[2][8][4];
    #pragma unroll
    for (int mi = 0; mi < 2; mi++)
        #pragma unroll
        for (int ni = 0; ni < 8; ni++)
            #pragma unroll
            for (int c = 0; c < 4; c++) acc[mi][ni][c] = 0.f;

    float4 ar[4];
    float4 br[4];

    const int a_row = tid >> 1;
    const int a_f4  = (tid & 1) * 4;
    const int b_col4 = tid & 31;

    auto loadA = [&](int k0) {
        const int mg = m0 + a_row;
        const int xbase = (k0 < 128 ? k0 : k0 - 128);
        float mult = 0.f;
        if (mg < n) mult = (k0 < 128) ? 1.f : t[mg];
        const float4* xr = (const float4*)&x[(size_t)(mg < n ? mg : 0) * 128 + xbase];
        #pragma unroll
        for (int i = 0; i < 4; i++) {
            float4 v = xr[a_f4 + i];
            ar[i].x = v.x * mult; ar[i].y = v.y * mult;
            ar[i].z = v.z * mult; ar[i].w = v.w * mult;
        }
    };
    auto storeA = [&]() {
        #pragma unroll
        for (int i = 0; i < 4; i++) {
            float4 v;
            v.x = __uint_as_float(f2tf(ar[i].x));
            v.y = __uint_as_float(f2tf(ar[i].y));
            v.z = __uint_as_float(f2tf(ar[i].z));
            v.w = __uint_as_float(f2tf(ar[i].w));
            *(float4*)&As[a_row][(a_f4 + i) * 4] = v;
        }
    };
    auto loadB = [&](int k0) {
        const int jj = b_col4 * 4;
        #pragma unroll
        for (int i = 0; i < 4; i++) {
            const int row = wid + i * 8;
            if (jj < bw) br[i] = *(const float4*)&Bmat[(size_t)(k0 + row) * bw + jj];
            else         br[i] = make_float4(0.f, 0.f, 0.f, 0.f);
        }
    };
    auto storeB = [&]() {
        const int jj = b_col4 * 4;
        #pragma unroll
        for (int i = 0; i < 4; i++) {
            const int row = wid + i * 8;
            float4 v;
            v.x = __uint_as_float(f2tf(br[i].x));
            v.y = __uint_as_float(f2tf(br[i].y));
            v.z = __uint_as_float(f2tf(br[i].z));
            v.w = __uint_as_float(f2tf(br[i].w));
            *(float4*)&Bs[row][jj] = v;
        }
    };

    loadA(0); loadB(0);
    storeA(); storeB();
    __syncthreads();

    for (int k0 = 0; k0 < 256; k0 += BK) {
        const bool has_next = (k0 + BK) < 256;
        if (has_next) { loadA(k0 + BK); loadB(k0 + BK); }

        #pragma unroll
        for (int ks = 0; ks < 4; ks++) {
            const int kk = ks * 8;
            unsigned afrag[2][4];
            #pragma unroll
            for (int mi = 0; mi < 2; mi++) {
                const int r0 = warp_m * 32 + mi * 16 + g;
                afrag[mi][0] = __float_as_uint(As[r0][kk + tig]);
                afrag[mi][1] = __float_as_uint(As[r0 + 8][kk + tig]);
                afrag[mi][2] = __float_as_uint(As[r0][kk + tig + 4]);
                afrag[mi][3] = __float_as_uint(As[r0 + 8][kk + tig + 4]);
            }
            #pragma unroll
            for (int ni = 0; ni < 8; ni++) {
                const int cb = warp_n * 64 + ni * 8 + g;
                const unsigned b0 = __float_as_uint(Bs[kk + tig][cb]);
                const unsigned b1 = __float_as_uint(Bs[kk + tig + 4][cb]);
                mma_tf32(acc[0][ni], afrag[0], b0, b1);
                mma_tf32(acc[1][ni], afrag[1], b0, b1);
            }
        }
        __syncthreads();
        if (has_next) { storeA(); storeB(); __syncthreads(); }
    }

    #pragma unroll
    for (int mi = 0; mi < 2; mi++) {
        const int row = warp_m * 32 + mi * 16 + g;
        #pragma unroll
        for (int ni = 0; ni < 8; ni++) {
            const int col = warp_n * 64 + ni * 8 + 2 * tig;
            if (col >= bw) continue;
            const float bb0 = bias[col];
            const float bb1 = bias[col + 1];
            const int mg0 = m0 + row;
            const int mg1 = m0 + row + 8;
            if (packed) {
                // packed half idx: mg*256 + (col>>2)*8 + (col&3) + voff
                const int hidx = ((col >> 2) << 3) + (col & 3) + voff;
                if (mg0 < n) {
                    __half2 h = __floats2half2_rn(acc[mi][ni][0] + bb0,
                                                  acc[mi][ni][1] + bb1);
                    *(__half2*)&g_kvh[(size_t)mg0 * 256 + hidx] = h;
                }
                if (mg1 < n) {
                    __half2 h = __floats2half2_rn(acc[mi][ni][2] + bb0,
                                                  acc[mi][ni][3] + bb1);
                    *(__half2*)&g_kvh[(size_t)mg1 * 256 + hidx] = h;
                }
            } else {
                if (mg0 < n) {
                    float2 o; o.x = acc[mi][ni][0] + bb0; o.y = acc[mi][ni][1] + bb1;
                    *(float2*)&outp[(size_t)mg0 * bw + col] = o;
                }
                if (mg1 < n) {
                    float2 o; o.x = acc[mi][ni][2] + bb0; o.y = acc[mi][ni][3] + bb1;
                    *(float2*)&outp[(size_t)mg1 * bw + col] = o;
                }
            }
        }
    }
}

// ================= CSR build ===============================================
__global__ void count_deg(const int* __restrict__ ei, int nE) {
    const int e = blockIdx.x * blockDim.x + threadIdx.x;
    if (e < nE) atomicAdd(&g_deg[ei[nE + e]], 1);
}

#define SCAN_B 1024
__global__ void scan1(int n) {
    __shared__ int sh[SCAN_B];
    const int tid = threadIdx.x;
    const int i = blockIdx.x * SCAN_B + tid;
    const int v = (i < n) ? g_deg[i] : 0;
    sh[tid] = v;
    __syncthreads();
    #pragma unroll
    for (int off = 1; off < SCAN_B; off <<= 1) {
        int u = (tid >= off) ? sh[tid - off] : 0;
        __syncthreads();
        sh[tid] += u;
        __syncthreads();
    }
    if (i < n) g_off[i] = sh[tid] - v;   // exclusive
    if (tid == SCAN_B - 1) g_bsums[blockIdx.x] = sh[tid];
}

__global__ void scan2(int nb) {
    __shared__ int sh[64];
    const int tid = threadIdx.x;
    const int v = (tid < nb) ? g_bsums[tid] : 0;
    sh[tid] = v;
    __syncthreads();
    #pragma unroll
    for (int off = 1; off < 64; off <<= 1) {
        int u = (tid >= off) ? sh[tid - off] : 0;
        __syncthreads();
        sh[tid] += u;
        __syncthreads();
    }
    if (tid < nb) g_bsums[tid] = sh[tid] - v;  // exclusive
}

__global__ void scan3(int n) {
    const int i = blockIdx.x * SCAN_B + threadIdx.x;
    if (i < n && blockIdx.x > 0) g_off[i] += g_bsums[blockIdx.x];
}

// bump g_off[dst] directly: after this kernel g_off[dst] = inclusive end.
__global__ void scatter_csr(const int* __restrict__ ei,
                            const float* __restrict__ ew, int nE) {
    const int e = blockIdx.x * blockDim.x + threadIdx.x;
    if (e >= nE) return;
    const int src = ei[e];
    const int dst = ei[nE + e];
    const int pos = atomicAdd(&g_off[dst], 1);
    int2 sw;
    sw.x = src;
    sw.y = __float_as_int(ew[e]);
    g_csr[pos] = sw;
}

// ============ Fused node pass: attention aggregate + epilogue ==============
// One warp per node; packed fp16 kv (1 LDG.128/lane/edge); edge-term algebra:
//   alpha = q.k + wt*(q.We) + q.be ;  Sum (v+e)p = Sum v p + We*Sum(wt p) + be*Sum p
__global__ void __launch_bounds__(256) node_kernel(
    const float* __restrict__ x,
    const float* __restrict__ We, const float* __restrict__ be,
    const float* __restrict__ Wmlp, const float* __restrict__ bmlp,
    float* __restrict__ out, int n)
{
    __shared__ float w_sh[32 * 256];
    __shared__ float bm_sh[256];
    for (int i = threadIdx.x; i < 32 * 256; i += 256) w_sh[i] = Wmlp[i];
    if (threadIdx.x < 256) bm_sh[threadIdx.x] = bmlp[threadIdx.x];
    __syncthreads();

    const int warp = threadIdx.x >> 5;
    const int lane = threadIdx.x & 31;
    const int nn = blockIdx.x * 8 + warp;
    if (nn >= n) return;

    const float4 We4 = ((const float4*)We)[lane];
    const float4 be4 = ((const float4*)be)[lane];
    const float4 q4 = ((const float4*)g_q)[nn * 32 + lane];

    // per-head dots q.We and q.be (replicated across the head's 8 lanes)
    float qWe = q4.x * We4.x + q4.y * We4.y + q4.z * We4.z + q4.w * We4.w;
    float qbe = q4.x * be4.x + q4.y * be4.y + q4.z * be4.z + q4.w * be4.w;
    #pragma unroll
    for (int m = 1; m <= 4; m <<= 1) {
        qWe += __shfl_xor_sync(0xffffffffu, qWe, m);
        qbe += __shfl_xor_sync(0xffffffffu, qbe, m);
    }

    const int cnt = g_deg[nn];
    const int end = g_off[nn];          // inclusive end (scatter bumped it)
    const int beg = end - cnt;

    float4 macc = make_float4(0.f, 0.f, 0.f, 0.f);
    float dsum = 0.f;   // Sum p        (per head)
    float wsum = 0.f;   // Sum wt*p     (per head)

    const uint4* kvp = (const uint4*)g_kvh;

    int j = beg;
    const int lim = beg + (cnt & ~3);
    for (; j < lim; j += 4) {
        int2 sw[4];
        #pragma unroll
        for (int i = 0; i < 4; i++) sw[i] = g_csr[j + i];
        uint4 raw[4];
        #pragma unroll
        for (int i = 0; i < 4; i++) raw[i] = kvp[sw[i].x * 32 + lane];

        float s[4];
        float4 vv[4];
        #pragma unroll
        for (int i = 0; i < 4; i++) {
            const float2 k01 = __half22float2(*(const __half2*)&raw[i].x);
            const float2 k23 = __half22float2(*(const __half2*)&raw[i].y);
            const float2 v01 = __half22float2(*(const __half2*)&raw[i].z);
            const float2 v23 = __half22float2(*(const __half2*)&raw[i].w);
            vv[i] = make_float4(v01.x, v01.y, v23.x, v23.y);
            s[i] = q4.x * k01.x + q4.y * k01.y + q4.z * k23.x + q4.w * k23.y;
        }
        #pragma unroll
        for (int i = 0; i < 4; i++) {
            s[i] += __shfl_xor_sync(0xffffffffu, s[i], 1);
            s[i] += __shfl_xor_sync(0xffffffffu, s[i], 2);
            s[i] += __shfl_xor_sync(0xffffffffu, s[i], 4);
        }
        #pragma unroll
        for (int i = 0; i < 4; i++) {
            const float wt = __int_as_float(sw[i].y);
            const float alpha = s[i] + fmaf(wt, qWe, qbe);
            const float p = __expf(alpha * 0.17677669529663689f);  // 1/sqrt(32)
            dsum += p;
            wsum = fmaf(wt, p, wsum);
            macc.x = fmaf(vv[i].x, p, macc.x);
            macc.y = fmaf(vv[i].y, p, macc.y);
            macc.z = fmaf(vv[i].z, p, macc.z);
            macc.w = fmaf(vv[i].w, p, macc.w);
        }
    }
    for (; j < end; j++) {
        const int2 sw = g_csr[j];
        const uint4 raw = kvp[sw.x * 32 + lane];
        const float2 k01 = __half22float2(*(const __half2*)&raw.x);
        const float2 k23 = __half22float2(*(const __half2*)&raw.y);
        const float2 v01 = __half22float2(*(const __half2*)&raw.z);
        const float2 v23 = __half22float2(*(const __half2*)&raw.w);
        float s = q4.x * k01.x + q4.y * k01.y + q4.z * k23.x + q4.w * k23.y;
        s += __shfl_xor_sync(0xffffffffu, s, 1);
        s += __shfl_xor_sync(0xffffffffu, s, 2);
        s += __shfl_xor_sync(0xffffffffu, s, 4);
        const float wt = __int_as_float(sw.y);
        const float alpha = s + fmaf(wt, qWe, qbe);
        const float p = __expf(alpha * 0.17677669529663689f);
        dsum += p;
        wsum = fmaf(wt, p, wsum);
        macc.x = fmaf(v01.x, p, macc.x);
        macc.y = fmaf(v01.y, p, macc.y);
        macc.z = fmaf(v23.x, p, macc.z);
        macc.w = fmaf(v23.y, p, macc.w);
    }

    // z = (Sum v p + We*Sum(wt p) + be*Sum p) / (Sum p + eps), per head
    const float inv = 1.f / (dsum + 1e-16f);
    float4 z4;
    z4.x = (macc.x + We4.x * wsum + be4.x * dsum) * inv;
    z4.y = (macc.y + We4.y * wsum + be4.y * dsum) * inv;
    z4.z = (macc.z + We4.z * wsum + be4.z * dsum) * inv;
    z4.w = (macc.w + We4.w * wsum + be4.w * dsum) * inv;

    #pragma unroll
    for (int m = 8; m <= 16; m <<= 1) {
        z4.x += __shfl_xor_sync(0xffffffffu, z4.x, m);
        z4.y += __shfl_xor_sync(0xffffffffu, z4.y, m);
        z4.z += __shfl_xor_sync(0xffffffffu, z4.z, m);
        z4.w += __shfl_xor_sync(0xffffffffu, z4.w, m);
    }

    const int u = lane & 7;
    const float4 sk = ((const float4*)g_skip)[nn * 8 + u];
    float4 y4;
    y4.x = tanhf(z4.x * 0.25f + sk.x);
    y4.y = tanhf(z4.y * 0.25f + sk.y);
    y4.z = tanhf(z4.z * 0.25f + sk.z);
    y4.w = tanhf(z4.w * 0.25f + sk.w);

    float accS[4] = {0.f, 0.f, 0.f, 0.f};
    float accH[4] = {0.f, 0.f, 0.f, 0.f};
    #pragma unroll
    for (int uu = 0; uu < 8; uu++) {
        const float b0 = __shfl_sync(0xffffffffu, y4.x, uu);
        const float b1 = __shfl_sync(0xffffffffu, y4.y, uu);
        const float b2 = __shfl_sync(0xffffffffu, y4.z, uu);
        const float b3 = __shfl_sync(0xffffffffu, y4.w, uu);
        const int d0 = 4 * uu;
        #pragma unroll
        for (int k = 0; k < 4; k++) {
            const int c = lane + 32 * k;
            accS[k] = fmaf(b0, w_sh[(d0 + 0) * 256 + c], accS[k]);
            accS[k] = fmaf(b1, w_sh[(d0 + 1) * 256 + c], accS[k]);
            accS[k] = fmaf(b2, w_sh[(d0 + 2) * 256 + c], accS[k]);
            accS[k] = fmaf(b3, w_sh[(d0 + 3) * 256 + c], accS[k]);
            accH[k] = fmaf(b0, w_sh[(d0 + 0) * 256 + 128 + c], accH[k]);
            accH[k] = fmaf(b1, w_sh[(d0 + 1) * 256 + 128 + c], accH[k]);
            accH[k] = fmaf(b2, w_sh[(d0 + 2) * 256 + 128 + c], accH[k]);
            accH[k] = fmaf(b3, w_sh[(d0 + 3) * 256 + 128 + c], accH[k]);
        }
    }
    #pragma unroll
    for (int k = 0; k < 4; k++) {
        const int c = lane + 32 * k;
        const float sc = tanhf(accS[k] + bm_sh[c]);
        const float sh = tanhf(accH[k] + bm_sh[128 + c]);
        out[(size_t)nn * 128 + c] = fmaf(x[(size_t)nn * 128 + c], sc, sh);
    }
}

// ================= launch ==================================================
extern "C" void kernel_launch(void* const* d_in, const int* in_sizes, int n_in,
                              void* d_out, int out_size)
{
    const float* x     = (const float*)d_in[0];
    const float* t     = (const float*)d_in[1];
    const int*   ei    = (const int*)  d_in[2];
    const float* ew    = (const float*)d_in[3];
    const float* Wq    = (const float*)d_in[4];
    const float* bq    = (const float*)d_in[5];
    const float* Wk    = (const float*)d_in[6];
    const float* bk    = (const float*)d_in[7];
    const float* Wv    = (const float*)d_in[8];
    const float* bv    = (const float*)d_in[9];
    const float* We    = (const float*)d_in[10];
    const float* be    = (const float*)d_in[11];
    const float* Wskip = (const float*)d_in[12];
    const float* bskip = (const float*)d_in[13];
    const float* Wmlp  = (const float*)d_in[14];
    const float* bmlp  = (const float*)d_in[15];
    float* out = (float*)d_out;

    const int n  = in_sizes[0] / 128;
    const int nE = in_sizes[3];

    // one-time side stream + fork/join events (same work every call)
    static cudaStream_t sB = nullptr;
    static cudaEvent_t evFork = nullptr, evJoin = nullptr;
    if (sB == nullptr) {
        cudaStreamCreateWithFlags(&sB, cudaStreamNonBlocking);
        cudaEventCreateWithFlags(&evFork, cudaEventDisableTiming);
        cudaEventCreateWithFlags(&evJoin, cudaEventDisableTiming);
    }

    void *degPtr = nullptr;
    cudaGetSymbolAddress(&degPtr, g_deg);

    // ---- fork: CSR build on side stream, GEMM on main stream -------------
    cudaEventRecord(evFork, 0);
    cudaStreamWaitEvent(sB, evFork, 0);

    cudaMemsetAsync(degPtr, 0, (size_t)n * sizeof(int), sB);
    count_deg<<<(nE + 255) / 256, 256, 0, sB>>>(ei, nE);
    const int nb = (n + SCAN_B - 1) / SCAN_B;
    scan1<<<nb, SCAN_B, 0, sB>>>(n);
    scan2<<<1, 64, 0, sB>>>(nb);
    scan3<<<nb, SCAN_B, 0, sB>>>(n);
    scatter_csr<<<(nE + 255) / 256, 256, 0, sB>>>(ei, ew, nE);
    cudaEventRecord(evJoin, sB);

    dim3 g1((n + BM - 1) / BM, 4);
    gemm_tf32<<<g1, 256>>>(x, t, Wq, bq, Wk, bk, Wv, bv, Wskip, bskip, n);

    // ---- join, then fused attention + epilogue ---------------------------
    cudaStreamWaitEvent(0, evJoin, 0);
    node_kernel<<<(n + 7) / 8, 256>>>(x, We, be, Wmlp, bmlp, out, n);
}